// round 2
// baseline (speedup 1.0000x reference)
#include <cuda_runtime.h>
#include <math.h>

#define NB 8
#define NF 128
#define LATD 256
#define NPIX 4096
#define NCALLS 16
#define FIN 384
#define FO 256
#define KT 197376

#define OFF_WIN  0
#define OFF_BIN  49152
#define OFF_WMID 49280
#define OFF_BMID 65664
#define OFF_WOUT 65792
#define OFF_BOUT 98560
#define OFF_WSH  98816
#define OFF_BSH  197120

// -------- scratch (static device globals; no allocation) --------
__device__ float g_kall[NB * KT];            // 6.3 MB
__device__ float g_p   [NB * FIN * NPIX];    // 50.3 MB
__device__ float g_h1  [NB * NF  * NPIX];    // 16.8 MB
__device__ float g_h2  [NB * NF  * NPIX];    // 16.8 MB
__device__ float g_dn  [NB * FO  * NPIX];    // 33.6 MB

// ======================================================================
// kall = (lat @ hyper_w + hyper_b) * segment_scale
// ======================================================================
__global__ void __launch_bounds__(256) hyper_kernel(
    const float* __restrict__ lat, const float* __restrict__ hw,
    const float* __restrict__ hb, float* __restrict__ kall)
{
    __shared__ float ls[NB * LATD];
    const int tid = threadIdx.x;
    for (int i = tid; i < NB * LATD; i += 256) ls[i] = lat[i];
    __syncthreads();

    const int n = blockIdx.x * 256 + tid;   // grid = 197376/256 = 771 exact
    float acc[NB];
#pragma unroll
    for (int b = 0; b < NB; b++) acc[b] = 0.f;

    for (int k = 0; k < LATD; k++) {
        float w = hw[(size_t)k * KT + n];
#pragma unroll
        for (int b = 0; b < NB; b++) acc[b] = fmaf(ls[b * LATD + k], w, acc[b]);
    }

    float s;
    if      (n < OFF_BIN)  s = 0.05103103630798288f;  // 1/sqrt(384)
    else if (n < OFF_WMID) s = 1.f;
    else if (n < OFF_BMID) s = 0.08838834764831845f;  // 1/sqrt(128)
    else if (n < OFF_WOUT) s = 1.f;
    else if (n < OFF_BOUT) s = 0.08838834764831845f;
    else if (n < OFF_WSH)  s = 1.f;
    else if (n < OFF_BSH)  s = 0.05103103630798288f;
    else                   s = 1.f;

    const float bias = hb[n];
#pragma unroll
    for (int b = 0; b < NB; b++)
        kall[(size_t)b * KT + n] = (acc[b] + bias) * s;
}

// ======================================================================
// build_p: p = instance_norm(concat([x, sobel_x(x), sobel_y(x)]))
// one block per (b, c) 64x64 plane
// ======================================================================
__global__ void __launch_bounds__(256) build_p_kernel(
    const float* __restrict__ X, float* __restrict__ P)
{
    const int c = blockIdx.x;
    const int b = blockIdx.y;
    const int tid = threadIdx.x;

    __shared__ float sp[68 * 68];
    __shared__ float red[8][6];
    __shared__ float stats[6];

    for (int i = tid; i < 68 * 68; i += 256) sp[i] = 0.f;
    __syncthreads();

    const float* Xp = X + ((size_t)b * NF + c) * NPIX;
    for (int i = tid; i < NPIX; i += 256) {
        int y = i >> 6, x = i & 63;
        sp[(y + 2) * 68 + (x + 2)] = Xp[i];
    }
    __syncthreads();

    const float C = 0.70710678118654752f;
    float vx[16], vsx[16], vsy[16];
    float s0 = 0.f, q0 = 0.f, s1 = 0.f, q1 = 0.f, s2 = 0.f, q2 = 0.f;

#pragma unroll
    for (int it = 0; it < 16; it++) {
        int pix = tid + it * 256;
        int y = pix >> 6, x = pix & 63;
        const float* B = &sp[y * 68 + x];   // B[i*68+j] = tap (i,j)

        float xv = B[2 * 68 + 2];
        float sx =
              C    * (B[1*68+4] - B[1*68+0]) + 0.5f * (B[1*68+3] - B[1*68+1])
            +        (B[2*68+4] - B[2*68+0]) + C    * (B[2*68+3] - B[2*68+1])
            + C    * (B[3*68+4] - B[3*68+0]) + 0.5f * (B[3*68+3] - B[3*68+1]);
        float sy =
              C    * (B[4*68+1] - B[0*68+1]) +        (B[4*68+2] - B[0*68+2])
            + C    * (B[4*68+3] - B[0*68+3])
            + 0.5f * (B[3*68+1] - B[1*68+1]) + C    * (B[3*68+2] - B[1*68+2])
            + 0.5f * (B[3*68+3] - B[1*68+3]);

        vx[it] = xv; vsx[it] = sx; vsy[it] = sy;
        s0 += xv; q0 = fmaf(xv, xv, q0);
        s1 += sx; q1 = fmaf(sx, sx, q1);
        s2 += sy; q2 = fmaf(sy, sy, q2);
    }

#pragma unroll
    for (int off = 16; off; off >>= 1) {
        s0 += __shfl_down_sync(0xffffffffu, s0, off);
        q0 += __shfl_down_sync(0xffffffffu, q0, off);
        s1 += __shfl_down_sync(0xffffffffu, s1, off);
        q1 += __shfl_down_sync(0xffffffffu, q1, off);
        s2 += __shfl_down_sync(0xffffffffu, s2, off);
        q2 += __shfl_down_sync(0xffffffffu, q2, off);
    }
    if ((tid & 31) == 0) {
        int w = tid >> 5;
        red[w][0] = s0; red[w][1] = q0; red[w][2] = s1;
        red[w][3] = q1; red[w][4] = s2; red[w][5] = q2;
    }
    __syncthreads();
    if (tid == 0) {
        float S[6] = {0.f, 0.f, 0.f, 0.f, 0.f, 0.f};
        for (int w = 0; w < 8; w++)
            for (int j = 0; j < 6; j++) S[j] += red[w][j];
        const float invN = 1.f / 4096.f;
#pragma unroll
        for (int t3 = 0; t3 < 3; t3++) {
            float mu  = S[2 * t3] * invN;
            float var = fmaxf(S[2 * t3 + 1] * invN - mu * mu, 0.f);
            stats[2 * t3]     = mu;
            stats[2 * t3 + 1] = rsqrtf(var + 1e-5f);
        }
    }
    __syncthreads();

    const float mu0 = stats[0], in0 = stats[1];
    const float mu1 = stats[2], in1 = stats[3];
    const float mu2 = stats[4], in2 = stats[5];

    float* P0 = P + ((size_t)b * FIN + c) * NPIX;
#pragma unroll
    for (int it = 0; it < 16; it++) {
        int pix = tid + it * 256;
        P0[pix]                        = (vx[it]  - mu0) * in0;
        P0[(size_t)NF  * NPIX + pix]   = (vsx[it] - mu1) * in1;
        P0[(size_t)2*NF * NPIX + pix]  = (vsy[it] - mu2) * in2;
    }
}

// ======================================================================
// 128x128 tiled SGEMM: Y[b,m,n] = sum_k W[b,m,k] X[b,k,n]  (+opt 2nd segment)
// BM=BN=128, BK=8, 256 threads, 8x8 per thread
// ======================================================================
__global__ void __launch_bounds__(256) gemm128_kernel(
    const float* __restrict__ kall,
    int w_off1, const float* __restrict__ X1, int K1,
    int w_off2, const float* __restrict__ X2, int K2,
    int b_off1, int b_off2,
    float* __restrict__ Y, int O, int act)
{
    const int b  = blockIdx.z;
    const int n0 = blockIdx.x * 128;
    const int m0 = blockIdx.y * 128;
    const int tid = threadIdx.x;

    __shared__ __align__(16) float Ws[8][132];
    __shared__ __align__(16) float Xs[8][132];

    float acc[8][8];
#pragma unroll
    for (int i = 0; i < 8; i++)
#pragma unroll
        for (int j = 0; j < 8; j++) acc[i][j] = 0.f;

    const int ty = tid >> 4;           // 0..15
    const int tx = tid & 15;           // 0..15
    const int lw_m = tid >> 1;         // 0..127
    const int lw_k = (tid & 1) * 4;    // 0 or 4
    const int lx_k = tid >> 5;         // 0..7
    const int lx_n = (tid & 31) * 4;   // 0..124

#pragma unroll 1
    for (int seg = 0; seg < 2; seg++) {
        const int K = seg ? K2 : K1;
        if (K == 0) continue;
        const float* W = kall + (size_t)b * KT + (seg ? w_off2 : w_off1);
        const float* X = (seg ? X2 : X1) + (size_t)b * K * NPIX;

        for (int k0 = 0; k0 < K; k0 += 8) {
            float4 wv = *reinterpret_cast<const float4*>(&W[(size_t)(m0 + lw_m) * K + k0 + lw_k]);
            float4 xv = *reinterpret_cast<const float4*>(&X[(size_t)(k0 + lx_k) * NPIX + n0 + lx_n]);
            __syncthreads();
            Ws[lw_k + 0][lw_m] = wv.x;
            Ws[lw_k + 1][lw_m] = wv.y;
            Ws[lw_k + 2][lw_m] = wv.z;
            Ws[lw_k + 3][lw_m] = wv.w;
            *reinterpret_cast<float4*>(&Xs[lx_k][lx_n]) = xv;
            __syncthreads();

#pragma unroll
            for (int k = 0; k < 8; k++) {
                float a[8], xr[8];
                *reinterpret_cast<float4*>(&a[0])  = *reinterpret_cast<const float4*>(&Ws[k][ty * 4]);
                *reinterpret_cast<float4*>(&a[4])  = *reinterpret_cast<const float4*>(&Ws[k][ty * 4 + 64]);
                *reinterpret_cast<float4*>(&xr[0]) = *reinterpret_cast<const float4*>(&Xs[k][tx * 4]);
                *reinterpret_cast<float4*>(&xr[4]) = *reinterpret_cast<const float4*>(&Xs[k][tx * 4 + 64]);
#pragma unroll
                for (int i = 0; i < 8; i++)
#pragma unroll
                    for (int j = 0; j < 8; j++)
                        acc[i][j] = fmaf(a[i], xr[j], acc[i][j]);
            }
        }
    }

    const float* bs1 = kall + (size_t)b * KT + b_off1;
    const float* bs2 = (b_off2 >= 0) ? (kall + (size_t)b * KT + b_off2) : nullptr;
    float* Yb = Y + (size_t)b * O * NPIX;

#pragma unroll
    for (int gi = 0; gi < 2; gi++)
#pragma unroll
        for (int ii = 0; ii < 4; ii++) {
            const int m = m0 + gi * 64 + ty * 4 + ii;
            float bv = bs1[m];
            if (bs2) bv += bs2[m];
#pragma unroll
            for (int gj = 0; gj < 2; gj++) {
                float4 o4;
                o4.x = acc[gi * 4 + ii][gj * 4 + 0] + bv;
                o4.y = acc[gi * 4 + ii][gj * 4 + 1] + bv;
                o4.z = acc[gi * 4 + ii][gj * 4 + 2] + bv;
                o4.w = acc[gi * 4 + ii][gj * 4 + 3] + bv;
                if (act) {
                    o4.x = fmaxf(o4.x, 0.f); o4.y = fmaxf(o4.y, 0.f);
                    o4.z = fmaxf(o4.z, 0.f); o4.w = fmaxf(o4.w, 0.f);
                }
                *reinterpret_cast<float4*>(&Yb[(size_t)m * NPIX + n0 + gj * 64 + tx * 4]) = o4;
            }
        }
}

// ======================================================================
// gated state update: x_new = x + leak * val * sigmoid(gate)
// ======================================================================
__global__ void __launch_bounds__(256) update_kernel(
    const float* __restrict__ dn, const float* __restrict__ xin,
    float* __restrict__ xout, const float* __restrict__ leakp)
{
    const int i = blockIdx.x * 256 + threadIdx.x;      // float4 index
    const float leak = fminf(fmaxf(leakp[0], 0.001f), 1000.f);
    const int b = i / 131072;                           // 128*4096/4
    const int r = i - b * 131072;

    const float4 v = reinterpret_cast<const float4*>(dn)[(size_t)b * 262144 + r];
    const float4 g = reinterpret_cast<const float4*>(dn)[(size_t)b * 262144 + 131072 + r];
    const float4 x = reinterpret_cast<const float4*>(xin)[i];
    float4 o;
    o.x = x.x + leak * v.x / (1.f + expf(-g.x));
    o.y = x.y + leak * v.y / (1.f + expf(-g.y));
    o.z = x.z + leak * v.z / (1.f + expf(-g.z));
    o.w = x.w + leak * v.w / (1.f + expf(-g.w));
    reinterpret_cast<float4*>(xout)[i] = o;
}

// ======================================================================
// 3x3 conv, 128->128 channels.  32 o-channels x (4 rows x 64 cols) per block.
// act=1: relu.  X0 != null: residual add.
// ======================================================================
__global__ void __launch_bounds__(256) conv3x3_kernel(
    const float* __restrict__ X, const float* __restrict__ W,
    const float* __restrict__ bias, const float* __restrict__ X0,
    float* __restrict__ Y, int act)
{
    const int b  = blockIdx.z;
    const int o0 = blockIdx.y * 32;
    const int y0 = blockIdx.x * 4;
    const int tid = threadIdx.x;
    const int og = tid >> 5;           // 0..7
    const int pg = tid & 31;
    const int r  = pg >> 3;            // 0..3
    const int xb = (pg & 7) * 8;       // 0..56

    __shared__ float sIn[6][66];
    __shared__ float sW[32 * 9];

    float acc[4][8];
#pragma unroll
    for (int oi = 0; oi < 4; oi++)
#pragma unroll
        for (int px = 0; px < 8; px++) acc[oi][px] = 0.f;

    const float* Xb = X + (size_t)b * NF * NPIX;

    for (int ci = 0; ci < NF; ci++) {
        __syncthreads();
        for (int i = tid; i < 6 * 66; i += 256) {
            int ry = i / 66, cx = i - ry * 66;
            int gy = y0 - 1 + ry, gx = cx - 1;
            float v = 0.f;
            if ((unsigned)gy < 64u && (unsigned)gx < 64u)
                v = Xb[(size_t)ci * NPIX + gy * 64 + gx];
            sIn[ry][cx] = v;
        }
        for (int i = tid; i < 288; i += 256) {
            int oi = i / 9, j = i - oi * 9;
            sW[i] = W[(size_t)(o0 + oi) * 1152 + ci * 9 + j];
        }
        __syncthreads();

        float in[3][10];
#pragma unroll
        for (int dy = 0; dy < 3; dy++)
#pragma unroll
            for (int dx = 0; dx < 10; dx++)
                in[dy][dx] = sIn[r + dy][xb + dx];

#pragma unroll
        for (int oi = 0; oi < 4; oi++) {
            float wr[9];
#pragma unroll
            for (int j = 0; j < 9; j++) wr[j] = sW[(og * 4 + oi) * 9 + j];
#pragma unroll
            for (int px = 0; px < 8; px++) {
                float s = acc[oi][px];
#pragma unroll
                for (int dy = 0; dy < 3; dy++)
#pragma unroll
                    for (int dx = 0; dx < 3; dx++)
                        s = fmaf(in[dy][px + dx], wr[dy * 3 + dx], s);
                acc[oi][px] = s;
            }
        }
    }

#pragma unroll
    for (int oi = 0; oi < 4; oi++) {
        const int o = o0 + og * 4 + oi;
        const float bv = bias[o];
#pragma unroll
        for (int px = 0; px < 8; px++) {
            size_t idx = ((size_t)b * NF + o) * NPIX + (size_t)(y0 + r) * 64 + xb + px;
            float v = acc[oi][px] + bv;
            if (X0) v += X0[idx];
            if (act) v = fmaxf(v, 0.f);
            Y[idx] = v;
        }
    }
}

// ======================================================================
// final 128->3 conv + clip; writes out_raw and out_img
// ======================================================================
__global__ void __launch_bounds__(256) conv_img_kernel(
    const float* __restrict__ X, const float* __restrict__ W,
    const float* __restrict__ bias,
    float* __restrict__ out_img, float* __restrict__ out_raw)
{
    const int b  = blockIdx.y;
    const int y0 = blockIdx.x * 4;
    const int tid = threadIdx.x;
    const int r = tid >> 6;
    const int x = tid & 63;

    __shared__ float sW[3 * 1152];
    __shared__ float sIn[6][66];

    for (int i = tid; i < 3 * 1152; i += 256) sW[i] = W[i];

    float acc[3] = {0.f, 0.f, 0.f};
    const float* Xb = X + (size_t)b * NF * NPIX;

    for (int ci = 0; ci < NF; ci++) {
        __syncthreads();
        for (int i = tid; i < 6 * 66; i += 256) {
            int ry = i / 66, cx = i - ry * 66;
            int gy = y0 - 1 + ry, gx = cx - 1;
            float v = 0.f;
            if ((unsigned)gy < 64u && (unsigned)gx < 64u)
                v = Xb[(size_t)ci * NPIX + gy * 64 + gx];
            sIn[ry][cx] = v;
        }
        __syncthreads();

        float in[9];
#pragma unroll
        for (int dy = 0; dy < 3; dy++)
#pragma unroll
            for (int dx = 0; dx < 3; dx++)
                in[dy * 3 + dx] = sIn[r + dy][x + dx];

#pragma unroll
        for (int o = 0; o < 3; o++) {
#pragma unroll
            for (int j = 0; j < 9; j++)
                acc[o] = fmaf(in[j], sW[o * 1152 + ci * 9 + j], acc[o]);
        }
    }

#pragma unroll
    for (int o = 0; o < 3; o++) {
        float v = acc[o] + bias[o];
        size_t idx = ((size_t)b * 3 + o) * NPIX + (size_t)(y0 + r) * 64 + x;
        out_raw[idx] = v;
        out_img[idx] = fminf(fmaxf(v, -1.f), 1.f);
    }
}

// ======================================================================
// launch
// ======================================================================
extern "C" void kernel_launch(void* const* d_in, const int* in_sizes, int n_in,
                              void* d_out, int out_size)
{
    const float* lat  = (const float*)d_in[0];
    const float* ca   = (const float*)d_in[1];
    const float* leak = (const float*)d_in[2];
    const float* hw   = (const float*)d_in[3];
    const float* hb   = (const float*)d_in[4];
    const float* rw1  = (const float*)d_in[5];
    const float* rb1  = (const float*)d_in[6];
    const float* rw2  = (const float*)d_in[7];
    const float* rb2  = (const float*)d_in[8];
    const float* iw   = (const float*)d_in[9];
    const float* ib   = (const float*)d_in[10];

    float* out = (float*)d_out;
    float* out_img = out;                                  // (8,3,64,64)
    float* embs    = out + 98304;                          // (17,8,128,64,64)
    float* out_raw = out + 98304 + (size_t)17 * 4194304;   // (8,3,64,64)

    float *kall, *p, *h1, *h2, *dn;
    cudaGetSymbolAddress((void**)&kall, g_kall);
    cudaGetSymbolAddress((void**)&p,    g_p);
    cudaGetSymbolAddress((void**)&h1,   g_h1);
    cudaGetSymbolAddress((void**)&h2,   g_h2);
    cudaGetSymbolAddress((void**)&dn,   g_dn);

    hyper_kernel<<<KT / 256, 256>>>(lat, hw, hb, kall);
    cudaMemcpyAsync(embs, ca, (size_t)4194304 * sizeof(float),
                    cudaMemcpyDeviceToDevice);

    for (int t = 0; t < NCALLS; t++) {
        float* x  = embs + (size_t)t * 4194304;
        float* xn = x + 4194304;

        build_p_kernel<<<dim3(NF, NB), 256>>>(x, p);

        // h1 = relu(W_in @ p + b_in)
        gemm128_kernel<<<dim3(32, 1, NB), 256>>>(
            kall, OFF_WIN, p, FIN, 0, nullptr, 0, OFF_BIN, -1, h1, NF, 1);
        // h2 = relu(W_mid @ h1 + b_mid)
        gemm128_kernel<<<dim3(32, 1, NB), 256>>>(
            kall, OFF_WMID, h1, NF, 0, nullptr, 0, OFF_BMID, -1, h2, NF, 1);
        // dn = W_out @ h2 + W_sh @ p + b_out + b_sh
        gemm128_kernel<<<dim3(32, 2, NB), 256>>>(
            kall, OFF_WOUT, h2, NF, OFF_WSH, p, FIN, OFF_BOUT, OFF_BSH, dn, FO, 0);

        update_kernel<<<4096, 256>>>(dn, x, xn, leak);
    }

    float* xf = embs + (size_t)NCALLS * 4194304;
    // h = relu(conv3x3(xf, res_w1) + res_b1)
    conv3x3_kernel<<<dim3(16, 4, NB), 256>>>(xf, rw1, rb1, nullptr, h1, 1);
    // y = xf + conv3x3(h, res_w2) + res_b2
    conv3x3_kernel<<<dim3(16, 4, NB), 256>>>(h1, rw2, rb2, xf, h2, 0);
    // out_raw / out_img
    conv_img_kernel<<<dim3(16, NB), 256>>>(h2, iw, ib, out_img, out_raw);
}

// round 4
// speedup vs baseline: 1.0799x; 1.0799x over previous
#include <cuda_runtime.h>
#include <cuda_bf16.h>
#include <mma.h>
#include <math.h>

using namespace nvcuda;

#define NB 8
#define NF 128
#define LATD 256
#define NPIX 4096
#define NCALLS 16
#define FIN 384
#define FO 256
#define KT 197376

#define OFF_WIN  0
#define OFF_BIN  49152
#define OFF_WMID 49280
#define OFF_BMID 65664
#define OFF_WOUT 65792
#define OFF_BOUT 98560
#define OFF_WSH  98816
#define OFF_BSH  197120

// -------- scratch --------
__device__ float g_kall[NB * KT];
__device__ float g_p [NB * FIN * NPIX];
__device__ float g_h1[NB * NF * NPIX];
__device__ float g_h2[NB * NF * NPIX];
__device__ __nv_bfloat16 g_w1h[NB * 128 * 384], g_w1l[NB * 128 * 384];
__device__ __nv_bfloat16 g_w2h[NB * 128 * 128], g_w2l[NB * 128 * 128];
__device__ __nv_bfloat16 g_w3h[NB * 256 * 512], g_w3l[NB * 256 * 512];

// split f = hi(bf16 truncate) + lo(bf16 rn of residual); packs pairs
__device__ __forceinline__ void split2(float a, float b, unsigned& hi, unsigned& lo) {
    unsigned ia = __float_as_uint(a), ib = __float_as_uint(b);
    unsigned ha = ia & 0xFFFF0000u, hb = ib & 0xFFFF0000u;
    float ra = a - __uint_as_float(ha);
    float rb = b - __uint_as_float(hb);
    hi = __byte_perm(ia, ib, 0x7632);
    __nv_bfloat162 l2 = __floats2bfloat162_rn(ra, rb);
    lo = *reinterpret_cast<unsigned*>(&l2);
}

// ======================================================================
// hyper: kall = (lat @ hyper_w + hyper_b) * segment_scale
// ======================================================================
__global__ void __launch_bounds__(256) hyper_kernel(
    const float* __restrict__ lat, const float* __restrict__ hw,
    const float* __restrict__ hb, float* __restrict__ kall)
{
    __shared__ float ls[NB * LATD];
    const int tid = threadIdx.x;
    for (int i = tid; i < NB * LATD; i += 256) ls[i] = lat[i];
    __syncthreads();
    const int n = blockIdx.x * 256 + tid;
    float acc[NB];
#pragma unroll
    for (int b = 0; b < NB; b++) acc[b] = 0.f;
    for (int k = 0; k < LATD; k++) {
        float w = hw[(size_t)k * KT + n];
#pragma unroll
        for (int b = 0; b < NB; b++) acc[b] = fmaf(ls[b * LATD + k], w, acc[b]);
    }
    float s;
    if      (n < OFF_BIN)  s = 0.05103103630798288f;
    else if (n < OFF_WMID) s = 1.f;
    else if (n < OFF_BMID) s = 0.08838834764831845f;
    else if (n < OFF_WOUT) s = 1.f;
    else if (n < OFF_BOUT) s = 0.08838834764831845f;
    else if (n < OFF_WSH)  s = 1.f;
    else if (n < OFF_BSH)  s = 0.05103103630798288f;
    else                   s = 1.f;
    const float bias = hb[n];
#pragma unroll
    for (int b = 0; b < NB; b++)
        kall[(size_t)b * KT + n] = (acc[b] + bias) * s;
}

// ======================================================================
// pack hypernet weights into bf16 hi/lo planes
// w1: [128][384]; w2: [128][128]; w3: [256][512] (k<128 = W_out, else W_sh)
// ======================================================================
__global__ void __launch_bounds__(256) pack_w_kernel(const float* __restrict__ kall)
{
    const int b = blockIdx.y;
    const int idx = blockIdx.x * 256 + threadIdx.x;   // 0..196607
    const float* ka = kall + (size_t)b * KT;
    float v; __nv_bfloat16 *dh, *dl;
    if (idx < 49152) {
        v = ka[OFF_WIN + idx];
        dh = g_w1h + (size_t)b * 49152 + idx; dl = g_w1l + (size_t)b * 49152 + idx;
    } else if (idx < 65536) {
        int i = idx - 49152;
        v = ka[OFF_WMID + i];
        dh = g_w2h + (size_t)b * 16384 + i;  dl = g_w2l + (size_t)b * 16384 + i;
    } else {
        int i = idx - 65536;
        int m = i >> 9, k = i & 511;
        v = (k < 128) ? ka[OFF_WOUT + m * 128 + k] : ka[OFF_WSH + m * 384 + (k - 128)];
        dh = g_w3h + (size_t)b * 131072 + i; dl = g_w3l + (size_t)b * 131072 + i;
    }
    unsigned iv = __float_as_uint(v) & 0xFFFF0000u;
    *dh = __ushort_as_bfloat16((unsigned short)(iv >> 16));
    *dl = __float2bfloat16(v - __uint_as_float(iv));
}

// ======================================================================
// build_p (channel-major fp32)
// ======================================================================
__global__ void __launch_bounds__(256) build_p_kernel(
    const float* __restrict__ X, float* __restrict__ P)
{
    const int c = blockIdx.x, b = blockIdx.y, tid = threadIdx.x;
    __shared__ float sp[68 * 68];
    __shared__ float red[8][6];
    __shared__ float stats[6];
    for (int i = tid; i < 68 * 68; i += 256) sp[i] = 0.f;
    __syncthreads();
    const float* Xp = X + ((size_t)b * NF + c) * NPIX;
    for (int i = tid; i < NPIX; i += 256) {
        int y = i >> 6, x = i & 63;
        sp[(y + 2) * 68 + (x + 2)] = Xp[i];
    }
    __syncthreads();
    const float C = 0.70710678118654752f;
    float vx[16], vsx[16], vsy[16];
    float s0 = 0.f, q0 = 0.f, s1 = 0.f, q1 = 0.f, s2 = 0.f, q2 = 0.f;
#pragma unroll
    for (int it = 0; it < 16; it++) {
        int pix = tid + it * 256;
        int y = pix >> 6, x = pix & 63;
        const float* B = &sp[y * 68 + x];
        float xv = B[2*68+2];
        float sx = C*(B[1*68+4]-B[1*68+0]) + 0.5f*(B[1*68+3]-B[1*68+1])
                 + (B[2*68+4]-B[2*68+0]) + C*(B[2*68+3]-B[2*68+1])
                 + C*(B[3*68+4]-B[3*68+0]) + 0.5f*(B[3*68+3]-B[3*68+1]);
        float sy = C*(B[4*68+1]-B[0*68+1]) + (B[4*68+2]-B[0*68+2])
                 + C*(B[4*68+3]-B[0*68+3])
                 + 0.5f*(B[3*68+1]-B[1*68+1]) + C*(B[3*68+2]-B[1*68+2])
                 + 0.5f*(B[3*68+3]-B[1*68+3]);
        vx[it] = xv; vsx[it] = sx; vsy[it] = sy;
        s0 += xv; q0 = fmaf(xv, xv, q0);
        s1 += sx; q1 = fmaf(sx, sx, q1);
        s2 += sy; q2 = fmaf(sy, sy, q2);
    }
#pragma unroll
    for (int off = 16; off; off >>= 1) {
        s0 += __shfl_down_sync(~0u, s0, off); q0 += __shfl_down_sync(~0u, q0, off);
        s1 += __shfl_down_sync(~0u, s1, off); q1 += __shfl_down_sync(~0u, q1, off);
        s2 += __shfl_down_sync(~0u, s2, off); q2 += __shfl_down_sync(~0u, q2, off);
    }
    if ((tid & 31) == 0) {
        int w = tid >> 5;
        red[w][0]=s0; red[w][1]=q0; red[w][2]=s1; red[w][3]=q1; red[w][4]=s2; red[w][5]=q2;
    }
    __syncthreads();
    if (tid == 0) {
        float S[6] = {0,0,0,0,0,0};
        for (int w = 0; w < 8; w++) for (int j = 0; j < 6; j++) S[j] += red[w][j];
        const float invN = 1.f / 4096.f;
#pragma unroll
        for (int t3 = 0; t3 < 3; t3++) {
            float mu = S[2*t3] * invN;
            float var = fmaxf(S[2*t3+1] * invN - mu*mu, 0.f);
            stats[2*t3] = mu; stats[2*t3+1] = rsqrtf(var + 1e-5f);
        }
    }
    __syncthreads();
    const float mu0 = stats[0], in0 = stats[1], mu1 = stats[2], in1 = stats[3],
                mu2 = stats[4], in2 = stats[5];
    float* P0 = P + ((size_t)b * FIN + c) * NPIX;
#pragma unroll
    for (int it = 0; it < 16; it++) {
        int pix = tid + it * 256;
        P0[pix]                       = (vx[it]  - mu0) * in0;
        P0[(size_t)NF*NPIX + pix]     = (vsx[it] - mu1) * in1;
        P0[(size_t)2*NF*NPIX + pix]   = (vsy[it] - mu2) * in2;
    }
}

// ======================================================================
// wmma bf16 GEMM, hi/lo 3-term:  Y[b,m,n] = sum_k W[b,m,k] B(k,n)
// MBLKS=1: CTA 128x128, relu+bias epilogue -> out fp32 channel-major
// MBLKS=2: CTA 256x64, gated update: out = xold + leak*val*sigmoid(gate)
// 256 threads = 8 warps, warp tile 32x64
// ======================================================================
template<int MBLKS>
__global__ void __launch_bounds__(256) gemm_wmma(
    const __nv_bfloat16* __restrict__ Wh, const __nv_bfloat16* __restrict__ Wl,
    int Ktot, const float* __restrict__ B1, int K1, const float* __restrict__ B2,
    const float* __restrict__ kall, int boff1, int boff2,
    float* __restrict__ out, const float* __restrict__ xold,
    const float* __restrict__ leakp)
{
    constexpr int MT = MBLKS * 128;
    constexpr int NT = 128 / MBLKS;
    constexpr int AW = 40;        // A smem ldm (elems)
    constexpr int BW = NT + 8;    // B smem ldm
    constexpr int EW = NT + 4;    // epilogue fp32 ldm

    extern __shared__ __align__(16) char sm[];
    __nv_bfloat16* Ah = (__nv_bfloat16*)sm;
    __nv_bfloat16* Al = Ah + MT * AW;
    __nv_bfloat16* Bh = Al + MT * AW;
    __nv_bfloat16* Bl = Bh + 32 * BW;
    float* Es = (float*)sm;

    const int tid = threadIdx.x;
    const int b = blockIdx.y;
    const int n0 = blockIdx.x * NT;
    const int wid = tid >> 5;
    const int wm = (MBLKS == 1) ? (wid >> 1) : wid;
    const int wn = (MBLKS == 1) ? (wid & 1) : 0;

    wmma::fragment<wmma::accumulator, 16, 16, 16, float> acc[2][4];
#pragma unroll
    for (int i = 0; i < 2; i++)
#pragma unroll
        for (int j = 0; j < 4; j++) wmma::fill_fragment(acc[i][j], 0.f);

    const __nv_bfloat16* WhB = Wh + (size_t)b * MT * Ktot;
    const __nv_bfloat16* WlB = Wl + (size_t)b * MT * Ktot;

    for (int kc = 0; kc < Ktot; kc += 32) {
        __syncthreads();
        // --- stage A chunk: MT x 32 bf16, hi+lo planes (uint4 = 8 bf16) ---
        for (int i = tid; i < MT * 8; i += 256) {
            int plane = (i >= MT * 4);
            int rem = plane ? i - MT * 4 : i;
            int m = rem >> 2, q = rem & 3;
            const __nv_bfloat16* s =
                (plane ? WlB : WhB) + (size_t)m * Ktot + kc + q * 8;
            uint4 v = *reinterpret_cast<const uint4*>(s);
            __nv_bfloat16* d = (plane ? Al : Ah) + m * AW + q * 8;
            *reinterpret_cast<uint4*>(d) = v;
        }
        // --- stage B chunk: 32 x NT fp32 -> hi/lo bf16 ---
        {
            const float* src; int ch0;
            if (kc < K1) { src = B1 + (size_t)b * K1 * NPIX; ch0 = kc; }
            else { src = B2 + (size_t)b * (Ktot - K1) * NPIX; ch0 = kc - K1; }
            constexpr int NC4 = NT / 4;
            for (int i = tid; i < 32 * NC4; i += 256) {
                int k = i / NC4, nc = (i - k * NC4) * 4;
                float4 v = *reinterpret_cast<const float4*>(
                    &src[(size_t)(ch0 + k) * NPIX + n0 + nc]);
                unsigned h0, l0, h1, l1;
                split2(v.x, v.y, h0, l0);
                split2(v.z, v.w, h1, l1);
                *reinterpret_cast<uint2*>(&Bh[k * BW + nc]) = make_uint2(h0, h1);
                *reinterpret_cast<uint2*>(&Bl[k * BW + nc]) = make_uint2(l0, l1);
            }
        }
        __syncthreads();

#pragma unroll
        for (int kk = 0; kk < 2; kk++) {
            wmma::fragment<wmma::matrix_a, 16, 16, 16, __nv_bfloat16, wmma::row_major> ah[2], al[2];
            wmma::fragment<wmma::matrix_b, 16, 16, 16, __nv_bfloat16, wmma::row_major> bh[4], bl[4];
#pragma unroll
            for (int i = 0; i < 2; i++) {
                wmma::load_matrix_sync(ah[i], Ah + (wm * 32 + i * 16) * AW + kk * 16, AW);
                wmma::load_matrix_sync(al[i], Al + (wm * 32 + i * 16) * AW + kk * 16, AW);
            }
#pragma unroll
            for (int j = 0; j < 4; j++) {
                wmma::load_matrix_sync(bh[j], Bh + kk * 16 * BW + wn * 64 + j * 16, BW);
                wmma::load_matrix_sync(bl[j], Bl + kk * 16 * BW + wn * 64 + j * 16, BW);
            }
#pragma unroll
            for (int i = 0; i < 2; i++)
#pragma unroll
                for (int j = 0; j < 4; j++) {
                    wmma::mma_sync(acc[i][j], ah[i], bh[j], acc[i][j]);
                    wmma::mma_sync(acc[i][j], ah[i], bl[j], acc[i][j]);
                    wmma::mma_sync(acc[i][j], al[i], bh[j], acc[i][j]);
                }
        }
    }

    __syncthreads();
#pragma unroll
    for (int i = 0; i < 2; i++)
#pragma unroll
        for (int j = 0; j < 4; j++)
            wmma::store_matrix_sync(Es + (wm * 32 + i * 16) * EW + wn * 64 + j * 16,
                                    acc[i][j], EW, wmma::mem_row_major);
    __syncthreads();

    const int m = tid >> 1, seg = tid & 1;
    if (MBLKS == 1) {
        const float bias = kall[(size_t)b * KT + boff1 + m];
        const size_t base = ((size_t)b * 128 + m) * NPIX + n0 + seg * 64;
        const float* er = Es + m * EW + seg * 64;
#pragma unroll
        for (int c = 0; c < 64; c += 4) {
            float4 o;
            o.x = fmaxf(er[c + 0] + bias, 0.f);
            o.y = fmaxf(er[c + 1] + bias, 0.f);
            o.z = fmaxf(er[c + 2] + bias, 0.f);
            o.w = fmaxf(er[c + 3] + bias, 0.f);
            *reinterpret_cast<float4*>(&out[base + c]) = o;
        }
    } else {
        const float leak = fminf(fmaxf(leakp[0], 0.001f), 1000.f);
        const float* ka = kall + (size_t)b * KT;
        const float bv = ka[boff1 + m] + ka[boff2 + m];
        const float bg = ka[boff1 + 128 + m] + ka[boff2 + 128 + m];
        const size_t base = ((size_t)b * 128 + m) * NPIX + n0 + seg * 32;
        const float* ev = Es + m * EW + seg * 32;
        const float* eg = Es + (m + 128) * EW + seg * 32;
#pragma unroll
        for (int c = 0; c < 32; c += 4) {
            float4 x = *reinterpret_cast<const float4*>(&xold[base + c]);
            float4 o;
            { float v = ev[c+0] + bv, g = eg[c+0] + bg; o.x = x.x + leak * v / (1.f + expf(-g)); }
            { float v = ev[c+1] + bv, g = eg[c+1] + bg; o.y = x.y + leak * v / (1.f + expf(-g)); }
            { float v = ev[c+2] + bv, g = eg[c+2] + bg; o.z = x.z + leak * v / (1.f + expf(-g)); }
            { float v = ev[c+3] + bv, g = eg[c+3] + bg; o.w = x.w + leak * v / (1.f + expf(-g)); }
            *reinterpret_cast<float4*>(&out[base + c]) = o;
        }
    }
}

// ======================================================================
// fp32 3x3 convs (known-correct)
// ======================================================================
__global__ void __launch_bounds__(256) conv3x3_kernel(
    const float* __restrict__ X, const float* __restrict__ W,
    const float* __restrict__ bias, const float* __restrict__ X0,
    float* __restrict__ Y, int act)
{
    const int b = blockIdx.z, o0 = blockIdx.y * 32, y0 = blockIdx.x * 4;
    const int tid = threadIdx.x;
    const int og = tid >> 5, pg = tid & 31, r = pg >> 3, xb = (pg & 7) * 8;
    __shared__ float sIn[6][66];
    __shared__ float sW[32 * 9];
    float acc[4][8];
#pragma unroll
    for (int oi = 0; oi < 4; oi++)
#pragma unroll
        for (int px = 0; px < 8; px++) acc[oi][px] = 0.f;
    const float* Xb = X + (size_t)b * NF * NPIX;
    for (int ci = 0; ci < NF; ci++) {
        __syncthreads();
        for (int i = tid; i < 6 * 66; i += 256) {
            int ry = i / 66, cx = i - ry * 66;
            int gy = y0 - 1 + ry, gx = cx - 1;
            float v = 0.f;
            if ((unsigned)gy < 64u && (unsigned)gx < 64u)
                v = Xb[(size_t)ci * NPIX + gy * 64 + gx];
            sIn[ry][cx] = v;
        }
        for (int i = tid; i < 288; i += 256) {
            int oi = i / 9, j = i - oi * 9;
            sW[i] = W[(size_t)(o0 + oi) * 1152 + ci * 9 + j];
        }
        __syncthreads();
        float in[3][10];
#pragma unroll
        for (int dy = 0; dy < 3; dy++)
#pragma unroll
            for (int dx = 0; dx < 10; dx++) in[dy][dx] = sIn[r + dy][xb + dx];
#pragma unroll
        for (int oi = 0; oi < 4; oi++) {
            float wr[9];
#pragma unroll
            for (int j = 0; j < 9; j++) wr[j] = sW[(og * 4 + oi) * 9 + j];
#pragma unroll
            for (int px = 0; px < 8; px++) {
                float s = acc[oi][px];
#pragma unroll
                for (int dy = 0; dy < 3; dy++)
#pragma unroll
                    for (int dx = 0; dx < 3; dx++)
                        s = fmaf(in[dy][px + dx], wr[dy * 3 + dx], s);
                acc[oi][px] = s;
            }
        }
    }
#pragma unroll
    for (int oi = 0; oi < 4; oi++) {
        const int o = o0 + og * 4 + oi;
        const float bvv = bias[o];
#pragma unroll
        for (int px = 0; px < 8; px++) {
            size_t idx = ((size_t)b * NF + o) * NPIX + (size_t)(y0 + r) * 64 + xb + px;
            float v = acc[oi][px] + bvv;
            if (X0) v += X0[idx];
            if (act) v = fmaxf(v, 0.f);
            Y[idx] = v;
        }
    }
}

__global__ void __launch_bounds__(256) conv_img_kernel(
    const float* __restrict__ X, const float* __restrict__ W,
    const float* __restrict__ bias,
    float* __restrict__ out_img, float* __restrict__ out_raw)
{
    const int b = blockIdx.y, y0 = blockIdx.x * 4, tid = threadIdx.x;
    const int r = tid >> 6, x = tid & 63;
    __shared__ float sW[3 * 1152];
    __shared__ float sIn[6][66];
    for (int i = tid; i < 3 * 1152; i += 256) sW[i] = W[i];
    float acc[3] = {0.f, 0.f, 0.f};
    const float* Xb = X + (size_t)b * NF * NPIX;
    for (int ci = 0; ci < NF; ci++) {
        __syncthreads();
        for (int i = tid; i < 6 * 66; i += 256) {
            int ry = i / 66, cx = i - ry * 66;
            int gy = y0 - 1 + ry, gx = cx - 1;
            float v = 0.f;
            if ((unsigned)gy < 64u && (unsigned)gx < 64u)
                v = Xb[(size_t)ci * NPIX + gy * 64 + gx];
            sIn[ry][cx] = v;
        }
        __syncthreads();
        float in[9];
#pragma unroll
        for (int dy = 0; dy < 3; dy++)
#pragma unroll
            for (int dx = 0; dx < 3; dx++) in[dy * 3 + dx] = sIn[r + dy][x + dx];
#pragma unroll
        for (int o = 0; o < 3; o++)
#pragma unroll
            for (int j = 0; j < 9; j++)
                acc[o] = fmaf(in[j], sW[o * 1152 + ci * 9 + j], acc[o]);
    }
#pragma unroll
    for (int o = 0; o < 3; o++) {
        float v = acc[o] + bias[o];
        size_t idx = ((size_t)b * 3 + o) * NPIX + (size_t)(y0 + r) * 64 + x;
        out_raw[idx] = v;
        out_img[idx] = fminf(fmaxf(v, -1.f), 1.f);
    }
}

// ======================================================================
extern "C" void kernel_launch(void* const* d_in, const int* in_sizes, int n_in,
                              void* d_out, int out_size)
{
    const float* lat  = (const float*)d_in[0];
    const float* ca   = (const float*)d_in[1];
    const float* leak = (const float*)d_in[2];
    const float* hw   = (const float*)d_in[3];
    const float* hb   = (const float*)d_in[4];
    const float* rw1  = (const float*)d_in[5];
    const float* rb1  = (const float*)d_in[6];
    const float* rw2  = (const float*)d_in[7];
    const float* rb2  = (const float*)d_in[8];
    const float* iw   = (const float*)d_in[9];
    const float* ib   = (const float*)d_in[10];

    float* out = (float*)d_out;
    float* out_img = out;
    float* embs    = out + 98304;
    float* out_raw = out + 98304 + (size_t)17 * 4194304;

    float *kall, *p, *h1, *h2;
    __nv_bfloat16 *w1h, *w1l, *w2h, *w2l, *w3h, *w3l;
    cudaGetSymbolAddress((void**)&kall, g_kall);
    cudaGetSymbolAddress((void**)&p,  g_p);
    cudaGetSymbolAddress((void**)&h1, g_h1);
    cudaGetSymbolAddress((void**)&h2, g_h2);
    cudaGetSymbolAddress((void**)&w1h, g_w1h);
    cudaGetSymbolAddress((void**)&w1l, g_w1l);
    cudaGetSymbolAddress((void**)&w2h, g_w2h);
    cudaGetSymbolAddress((void**)&w2l, g_w2l);
    cudaGetSymbolAddress((void**)&w3h, g_w3h);
    cudaGetSymbolAddress((void**)&w3l, g_w3l);

    const int SM1 = 128 * 132 * 4;   // 67584
    const int SM2 = 256 * 68 * 4;    // 69632
    cudaFuncSetAttribute(gemm_wmma<1>, cudaFuncAttributeMaxDynamicSharedMemorySize, SM1);
    cudaFuncSetAttribute(gemm_wmma<2>, cudaFuncAttributeMaxDynamicSharedMemorySize, SM2);

    hyper_kernel<<<KT / 256, 256>>>(lat, hw, hb, kall);
    pack_w_kernel<<<dim3(768, NB), 256>>>(kall);
    cudaMemcpyAsync(embs, ca, (size_t)4194304 * sizeof(float), cudaMemcpyDeviceToDevice);

    for (int t = 0; t < NCALLS; t++) {
        float* x  = embs + (size_t)t * 4194304;
        float* xn = x + 4194304;

        build_p_kernel<<<dim3(NF, NB), 256>>>(x, p);
        // h1 = relu(W_in @ p + b_in)
        gemm_wmma<1><<<dim3(32, NB), 256, SM1>>>(w1h, w1l, 384, p, 384, nullptr,
                                                 kall, OFF_BIN, 0, h1, nullptr, nullptr);
        // h2 = relu(W_mid @ h1 + b_mid)
        gemm_wmma<1><<<dim3(32, NB), 256, SM1>>>(w2h, w2l, 128, h1, 128, nullptr,
                                                 kall, OFF_BMID, 0, h2, nullptr, nullptr);
        // dn = W_out@h2 + W_sh@p (+biases); xn = x + leak*val*sigmoid(gate)
        gemm_wmma<2><<<dim3(64, NB), 256, SM2>>>(w3h, w3l, 512, h2, 128, p,
                                                 kall, OFF_BOUT, OFF_BSH, xn, x, leak);
    }

    float* xf = embs + (size_t)NCALLS * 4194304;
    conv3x3_kernel<<<dim3(16, 4, NB), 256>>>(xf, rw1, rb1, nullptr, h1, 1);
    conv3x3_kernel<<<dim3(16, 4, NB), 256>>>(h1, rw2, rb2, xf, h2, 0);
    conv_img_kernel<<<dim3(16, NB), 256>>>(h2, iw, ib, out_img, out_raw);
}

// round 5
// speedup vs baseline: 1.3143x; 1.2170x over previous
#include <cuda_runtime.h>
#include <cuda_bf16.h>
#include <mma.h>
#include <math.h>

using namespace nvcuda;

#define NB 8
#define NF 128
#define LATD 256
#define NPIX 4096
#define NCALLS 16
#define FIN 384
#define FO 256
#define KT 197376

#define OFF_WIN  0
#define OFF_BIN  49152
#define OFF_WMID 49280
#define OFF_BMID 65664
#define OFF_WOUT 65792
#define OFF_BOUT 98560
#define OFF_WSH  98816
#define OFF_BSH  197120

// -------- scratch (device globals, 16B aligned for vector/cp.async) --------
__device__ __align__(16) float g_kall[NB * KT];
__device__ __align__(16) __nv_bfloat16 g_ph[NB * FIN * NPIX], g_pl[NB * FIN * NPIX];
__device__ __align__(16) __nv_bfloat16 g_h1h[NB * NF * NPIX], g_h1l[NB * NF * NPIX];
__device__ __align__(16) __nv_bfloat16 g_h2h[NB * NF * NPIX], g_h2l[NB * NF * NPIX];
__device__ __align__(16) __nv_bfloat16 g_w1h[NB * 128 * 384], g_w1l[NB * 128 * 384];
__device__ __align__(16) __nv_bfloat16 g_w2h[NB * 128 * 128], g_w2l[NB * 128 * 128];
__device__ __align__(16) __nv_bfloat16 g_w3h[NB * 256 * 512], g_w3l[NB * 256 * 512];
__device__ __align__(16) float g_c1[NB * NF * NPIX];
__device__ __align__(16) float g_c2[NB * NF * NPIX];

#define CP16(dst, src) \
    asm volatile("cp.async.cg.shared.global [%0], [%1], 16;\n" :: "r"(dst), "l"(src))
#define CP_COMMIT() asm volatile("cp.async.commit_group;\n" ::: "memory")
#define CP_WAIT(n)  asm volatile("cp.async.wait_group %0;\n" :: "n"(n) : "memory")

// split f = hi(bf16 truncate) + lo(bf16 rn of residual)
__device__ __forceinline__ void split1(float v, __nv_bfloat16& h, __nv_bfloat16& l) {
    unsigned iv = __float_as_uint(v) & 0xFFFF0000u;
    h = __ushort_as_bfloat16((unsigned short)(iv >> 16));
    l = __float2bfloat16(v - __uint_as_float(iv));
}

// ======================================================================
// hyper: kall = (lat @ hyper_w + hyper_b) * segment_scale
// ======================================================================
__global__ void __launch_bounds__(256) hyper_kernel(
    const float* __restrict__ lat, const float* __restrict__ hw,
    const float* __restrict__ hb, float* __restrict__ kall)
{
    __shared__ float ls[NB * LATD];
    const int tid = threadIdx.x;
    for (int i = tid; i < NB * LATD; i += 256) ls[i] = lat[i];
    __syncthreads();
    const int n = blockIdx.x * 256 + tid;
    float acc[NB];
#pragma unroll
    for (int b = 0; b < NB; b++) acc[b] = 0.f;
    for (int k = 0; k < LATD; k++) {
        float w = hw[(size_t)k * KT + n];
#pragma unroll
        for (int b = 0; b < NB; b++) acc[b] = fmaf(ls[b * LATD + k], w, acc[b]);
    }
    float s;
    if      (n < OFF_BIN)  s = 0.05103103630798288f;
    else if (n < OFF_WMID) s = 1.f;
    else if (n < OFF_BMID) s = 0.08838834764831845f;
    else if (n < OFF_WOUT) s = 1.f;
    else if (n < OFF_BOUT) s = 0.08838834764831845f;
    else if (n < OFF_WSH)  s = 1.f;
    else if (n < OFF_BSH)  s = 0.05103103630798288f;
    else                   s = 1.f;
    const float bias = hb[n];
#pragma unroll
    for (int b = 0; b < NB; b++)
        kall[(size_t)b * KT + n] = (acc[b] + bias) * s;
}

// ======================================================================
// pack hypernet weights into bf16 hi/lo planes
// ======================================================================
__global__ void __launch_bounds__(256) pack_w_kernel(const float* __restrict__ kall)
{
    const int b = blockIdx.y;
    const int idx = blockIdx.x * 256 + threadIdx.x;
    const float* ka = kall + (size_t)b * KT;
    float v; __nv_bfloat16 *dh, *dl;
    if (idx < 49152) {
        v = ka[OFF_WIN + idx];
        dh = g_w1h + (size_t)b * 49152 + idx; dl = g_w1l + (size_t)b * 49152 + idx;
    } else if (idx < 65536) {
        int i = idx - 49152;
        v = ka[OFF_WMID + i];
        dh = g_w2h + (size_t)b * 16384 + i;  dl = g_w2l + (size_t)b * 16384 + i;
    } else {
        int i = idx - 65536;
        int m = i >> 9, k = i & 511;
        v = (k < 128) ? ka[OFF_WOUT + m * 128 + k] : ka[OFF_WSH + m * 384 + (k - 128)];
        dh = g_w3h + (size_t)b * 131072 + i; dl = g_w3l + (size_t)b * 131072 + i;
    }
    split1(v, *dh, *dl);
}

// ======================================================================
// build_p: instance-norm(concat[x, sobel_x, sobel_y]) -> hi/lo bf16 planes
// ======================================================================
__global__ void __launch_bounds__(256) build_p_kernel(
    const float* __restrict__ X, __nv_bfloat16* __restrict__ Ph,
    __nv_bfloat16* __restrict__ Pl)
{
    const int c = blockIdx.x, b = blockIdx.y, tid = threadIdx.x;
    __shared__ float sp[68 * 68];
    __shared__ float red[8][6];
    __shared__ float stats[6];
    for (int i = tid; i < 68 * 68; i += 256) sp[i] = 0.f;
    __syncthreads();
    const float* Xp = X + ((size_t)b * NF + c) * NPIX;
    for (int i = tid; i < NPIX; i += 256) {
        int y = i >> 6, x = i & 63;
        sp[(y + 2) * 68 + (x + 2)] = Xp[i];
    }
    __syncthreads();
    const float C = 0.70710678118654752f;
    float vx[16], vsx[16], vsy[16];
    float s0 = 0.f, q0 = 0.f, s1 = 0.f, q1 = 0.f, s2 = 0.f, q2 = 0.f;
#pragma unroll
    for (int it = 0; it < 16; it++) {
        int pix = tid + it * 256;
        int y = pix >> 6, x = pix & 63;
        const float* B = &sp[y * 68 + x];
        float xv = B[2*68+2];
        float sx = C*(B[1*68+4]-B[1*68+0]) + 0.5f*(B[1*68+3]-B[1*68+1])
                 + (B[2*68+4]-B[2*68+0]) + C*(B[2*68+3]-B[2*68+1])
                 + C*(B[3*68+4]-B[3*68+0]) + 0.5f*(B[3*68+3]-B[3*68+1]);
        float sy = C*(B[4*68+1]-B[0*68+1]) + (B[4*68+2]-B[0*68+2])
                 + C*(B[4*68+3]-B[0*68+3])
                 + 0.5f*(B[3*68+1]-B[1*68+1]) + C*(B[3*68+2]-B[1*68+2])
                 + 0.5f*(B[3*68+3]-B[1*68+3]);
        vx[it] = xv; vsx[it] = sx; vsy[it] = sy;
        s0 += xv; q0 = fmaf(xv, xv, q0);
        s1 += sx; q1 = fmaf(sx, sx, q1);
        s2 += sy; q2 = fmaf(sy, sy, q2);
    }
#pragma unroll
    for (int off = 16; off; off >>= 1) {
        s0 += __shfl_down_sync(~0u, s0, off); q0 += __shfl_down_sync(~0u, q0, off);
        s1 += __shfl_down_sync(~0u, s1, off); q1 += __shfl_down_sync(~0u, q1, off);
        s2 += __shfl_down_sync(~0u, s2, off); q2 += __shfl_down_sync(~0u, q2, off);
    }
    if ((tid & 31) == 0) {
        int w = tid >> 5;
        red[w][0]=s0; red[w][1]=q0; red[w][2]=s1; red[w][3]=q1; red[w][4]=s2; red[w][5]=q2;
    }
    __syncthreads();
    if (tid == 0) {
        float S[6] = {0,0,0,0,0,0};
        for (int w = 0; w < 8; w++) for (int j = 0; j < 6; j++) S[j] += red[w][j];
        const float invN = 1.f / 4096.f;
#pragma unroll
        for (int t3 = 0; t3 < 3; t3++) {
            float mu = S[2*t3] * invN;
            float var = fmaxf(S[2*t3+1] * invN - mu*mu, 0.f);
            stats[2*t3] = mu; stats[2*t3+1] = rsqrtf(var + 1e-5f);
        }
    }
    __syncthreads();
    const float mu0 = stats[0], in0 = stats[1], mu1 = stats[2], in1 = stats[3],
                mu2 = stats[4], in2 = stats[5];
    const size_t p0 = ((size_t)b * FIN + c) * NPIX;
#pragma unroll
    for (int it = 0; it < 16; it++) {
        int pix = tid + it * 256;
        float v0 = (vx[it]  - mu0) * in0;
        float v1 = (vsx[it] - mu1) * in1;
        float v2 = (vsy[it] - mu2) * in2;
        __nv_bfloat16 h, l;
        split1(v0, h, l); Ph[p0 + pix] = h; Pl[p0 + pix] = l;
        split1(v1, h, l); Ph[p0 + (size_t)NF*NPIX + pix] = h;   Pl[p0 + (size_t)NF*NPIX + pix] = l;
        split1(v2, h, l); Ph[p0 + (size_t)2*NF*NPIX + pix] = h; Pl[p0 + (size_t)2*NF*NPIX + pix] = l;
    }
}

// ======================================================================
// wmma bf16 GEMM, hi/lo 3-term, cp.async double-buffered.
// MBLKS=1: CTA 128x128, relu+bias -> hi/lo bf16 planes
// MBLKS=2: CTA 256x64, gated update -> fp32 new state
// ======================================================================
template<int MBLKS>
__global__ void __launch_bounds__(256, 2) gemm_wmma(
    const __nv_bfloat16* __restrict__ Wh, const __nv_bfloat16* __restrict__ Wl,
    int Ktot,
    const __nv_bfloat16* __restrict__ B1h, const __nv_bfloat16* __restrict__ B1l,
    int K1,
    const __nv_bfloat16* __restrict__ B2h, const __nv_bfloat16* __restrict__ B2l,
    const float* __restrict__ kall, int boff1, int boff2,
    float* __restrict__ outf,
    __nv_bfloat16* __restrict__ outh, __nv_bfloat16* __restrict__ outl,
    const float* __restrict__ xold, const float* __restrict__ leakp)
{
    constexpr int MT = MBLKS * 128;
    constexpr int NT = 128 / MBLKS;
    constexpr int AW = 40;
    constexpr int BW = NT + 8;
    constexpr int EW = NT + 4;
    constexpr int BUFE = 2 * MT * AW + 2 * 32 * BW;   // bf16 elems per stage buffer

    extern __shared__ __align__(16) char sm[];
    __nv_bfloat16* smB = (__nv_bfloat16*)sm;
    float* Es = (float*)sm;

    const int tid = threadIdx.x;
    const int b = blockIdx.y;
    const int n0 = blockIdx.x * NT;
    const int wid = tid >> 5;
    const int wm = (MBLKS == 1) ? (wid >> 1) : wid;
    const int wn = (MBLKS == 1) ? (wid & 1) : 0;

    const __nv_bfloat16* WhB = Wh + (size_t)b * MT * Ktot;
    const __nv_bfloat16* WlB = Wl + (size_t)b * MT * Ktot;

    wmma::fragment<wmma::accumulator, 16, 16, 16, float> acc[2][4];
#pragma unroll
    for (int i = 0; i < 2; i++)
#pragma unroll
        for (int j = 0; j < 4; j++) wmma::fill_fragment(acc[i][j], 0.f);

    auto stage = [&](int kc, int s) {
        __nv_bfloat16* Ahd = smB + (size_t)s * BUFE;
        __nv_bfloat16* Ald = Ahd + MT * AW;
        __nv_bfloat16* Bhd = Ald + MT * AW;
        __nv_bfloat16* Bld = Bhd + 32 * BW;
        // A chunk: MT x 32 bf16 x 2 planes, 16B pieces
#pragma unroll
        for (int i = tid; i < MT * 8; i += 256) {
            int plane = (i >= MT * 4);
            int rem = i - plane * MT * 4;
            int m = rem >> 2, q = rem & 3;
            const __nv_bfloat16* src = (plane ? WlB : WhB) + (size_t)m * Ktot + kc + q * 8;
            unsigned d = (unsigned)__cvta_generic_to_shared(
                (plane ? Ald : Ahd) + m * AW + q * 8);
            CP16(d, src);
        }
        // B chunk: 32 x NT bf16 x 2 planes
        const __nv_bfloat16 *sh, *sl; int ch0;
        if (kc < K1) {
            sh = B1h + (size_t)b * K1 * NPIX; sl = B1l + (size_t)b * K1 * NPIX; ch0 = kc;
        } else {
            int K2 = Ktot - K1;
            sh = B2h + (size_t)b * K2 * NPIX; sl = B2l + (size_t)b * K2 * NPIX; ch0 = kc - K1;
        }
        constexpr int NC8 = NT / 8;
#pragma unroll
        for (int i = tid; i < 32 * NC8 * 2; i += 256) {
            int plane = (i >= 32 * NC8);
            int rem = i - plane * 32 * NC8;
            int k = rem / NC8, c = (rem - k * NC8) * 8;
            const __nv_bfloat16* src = (plane ? sl : sh) + (size_t)(ch0 + k) * NPIX + n0 + c;
            unsigned d = (unsigned)__cvta_generic_to_shared(
                (plane ? Bld : Bhd) + k * BW + c);
            CP16(d, src);
        }
        CP_COMMIT();
    };

    auto compute = [&](int s) {
        const __nv_bfloat16* Ahd = smB + (size_t)s * BUFE;
        const __nv_bfloat16* Ald = Ahd + MT * AW;
        const __nv_bfloat16* Bhd = Ald + MT * AW;
        const __nv_bfloat16* Bld = Bhd + 32 * BW;
#pragma unroll
        for (int kk = 0; kk < 2; kk++) {
            wmma::fragment<wmma::matrix_a, 16, 16, 16, __nv_bfloat16, wmma::row_major> ah[2], al[2];
            wmma::fragment<wmma::matrix_b, 16, 16, 16, __nv_bfloat16, wmma::row_major> bh[4], bl[4];
#pragma unroll
            for (int i = 0; i < 2; i++) {
                wmma::load_matrix_sync(ah[i], Ahd + (wm * 32 + i * 16) * AW + kk * 16, AW);
                wmma::load_matrix_sync(al[i], Ald + (wm * 32 + i * 16) * AW + kk * 16, AW);
            }
#pragma unroll
            for (int j = 0; j < 4; j++) {
                wmma::load_matrix_sync(bh[j], Bhd + kk * 16 * BW + wn * 64 + j * 16, BW);
                wmma::load_matrix_sync(bl[j], Bld + kk * 16 * BW + wn * 64 + j * 16, BW);
            }
#pragma unroll
            for (int i = 0; i < 2; i++)
#pragma unroll
                for (int j = 0; j < 4; j++) {
                    wmma::mma_sync(acc[i][j], ah[i], bh[j], acc[i][j]);
                    wmma::mma_sync(acc[i][j], ah[i], bl[j], acc[i][j]);
                    wmma::mma_sync(acc[i][j], al[i], bh[j], acc[i][j]);
                }
        }
    };

    const int nch = Ktot >> 5;
    stage(0, 0);
    for (int ic = 0; ic < nch; ic++) {
        if (ic + 1 < nch) {
            stage((ic + 1) * 32, (ic + 1) & 1);
            CP_WAIT(1);
        } else {
            CP_WAIT(0);
        }
        __syncthreads();
        compute(ic & 1);
        __syncthreads();
    }

#pragma unroll
    for (int i = 0; i < 2; i++)
#pragma unroll
        for (int j = 0; j < 4; j++)
            wmma::store_matrix_sync(Es + (wm * 32 + i * 16) * EW + wn * 64 + j * 16,
                                    acc[i][j], EW, wmma::mem_row_major);
    __syncthreads();

    const int m = tid >> 1, seg = tid & 1;
    if (MBLKS == 1) {
        const float bias = kall[(size_t)b * KT + boff1 + m];
        const size_t base = ((size_t)b * 128 + m) * NPIX + n0 + seg * 64;
        const float* er = Es + m * EW + seg * 64;
#pragma unroll
        for (int c = 0; c < 64; c += 2) {
            float v0 = fmaxf(er[c + 0] + bias, 0.f);
            float v1 = fmaxf(er[c + 1] + bias, 0.f);
            __nv_bfloat16 h0, l0, h1, l1;
            split1(v0, h0, l0);
            split1(v1, h1, l1);
            __nv_bfloat162 hp; hp.x = h0; hp.y = h1;
            __nv_bfloat162 lp; lp.x = l0; lp.y = l1;
            *reinterpret_cast<__nv_bfloat162*>(&outh[base + c]) = hp;
            *reinterpret_cast<__nv_bfloat162*>(&outl[base + c]) = lp;
        }
    } else {
        const float leak = fminf(fmaxf(leakp[0], 0.001f), 1000.f);
        const float* ka = kall + (size_t)b * KT;
        const float bv = ka[boff1 + m] + ka[boff2 + m];
        const float bg = ka[boff1 + 128 + m] + ka[boff2 + 128 + m];
        const size_t base = ((size_t)b * 128 + m) * NPIX + n0 + seg * 32;
        const float* ev = Es + m * EW + seg * 32;
        const float* eg = Es + (m + 128) * EW + seg * 32;
#pragma unroll
        for (int c = 0; c < 32; c += 4) {
            float4 x = *reinterpret_cast<const float4*>(&xold[base + c]);
            float4 o;
            { float v = ev[c+0] + bv, g = eg[c+0] + bg; o.x = x.x + leak * v / (1.f + expf(-g)); }
            { float v = ev[c+1] + bv, g = eg[c+1] + bg; o.y = x.y + leak * v / (1.f + expf(-g)); }
            { float v = ev[c+2] + bv, g = eg[c+2] + bg; o.z = x.z + leak * v / (1.f + expf(-g)); }
            { float v = ev[c+3] + bv, g = eg[c+3] + bg; o.w = x.w + leak * v / (1.f + expf(-g)); }
            *reinterpret_cast<float4*>(&outf[base + c]) = o;
        }
    }
}

// ======================================================================
// fp32 3x3 convs (known-correct)
// ======================================================================
__global__ void __launch_bounds__(256) conv3x3_kernel(
    const float* __restrict__ X, const float* __restrict__ W,
    const float* __restrict__ bias, const float* __restrict__ X0,
    float* __restrict__ Y, int act)
{
    const int b = blockIdx.z, o0 = blockIdx.y * 32, y0 = blockIdx.x * 4;
    const int tid = threadIdx.x;
    const int og = tid >> 5, pg = tid & 31, r = pg >> 3, xb = (pg & 7) * 8;
    __shared__ float sIn[6][66];
    __shared__ float sW[32 * 9];
    float acc[4][8];
#pragma unroll
    for (int oi = 0; oi < 4; oi++)
#pragma unroll
        for (int px = 0; px < 8; px++) acc[oi][px] = 0.f;
    const float* Xb = X + (size_t)b * NF * NPIX;
    for (int ci = 0; ci < NF; ci++) {
        __syncthreads();
        for (int i = tid; i < 6 * 66; i += 256) {
            int ry = i / 66, cx = i - ry * 66;
            int gy = y0 - 1 + ry, gx = cx - 1;
            float v = 0.f;
            if ((unsigned)gy < 64u && (unsigned)gx < 64u)
                v = Xb[(size_t)ci * NPIX + gy * 64 + gx];
            sIn[ry][cx] = v;
        }
        for (int i = tid; i < 288; i += 256) {
            int oi = i / 9, j = i - oi * 9;
            sW[i] = W[(size_t)(o0 + oi) * 1152 + ci * 9 + j];
        }
        __syncthreads();
        float in[3][10];
#pragma unroll
        for (int dy = 0; dy < 3; dy++)
#pragma unroll
            for (int dx = 0; dx < 10; dx++) in[dy][dx] = sIn[r + dy][xb + dx];
#pragma unroll
        for (int oi = 0; oi < 4; oi++) {
            float wr[9];
#pragma unroll
            for (int j = 0; j < 9; j++) wr[j] = sW[(og * 4 + oi) * 9 + j];
#pragma unroll
            for (int px = 0; px < 8; px++) {
                float s = acc[oi][px];
#pragma unroll
                for (int dy = 0; dy < 3; dy++)
#pragma unroll
                    for (int dx = 0; dx < 3; dx++)
                        s = fmaf(in[dy][px + dx], wr[dy * 3 + dx], s);
                acc[oi][px] = s;
            }
        }
    }
#pragma unroll
    for (int oi = 0; oi < 4; oi++) {
        const int o = o0 + og * 4 + oi;
        const float bvv = bias[o];
#pragma unroll
        for (int px = 0; px < 8; px++) {
            size_t idx = ((size_t)b * NF + o) * NPIX + (size_t)(y0 + r) * 64 + xb + px;
            float v = acc[oi][px] + bvv;
            if (X0) v += X0[idx];
            if (act) v = fmaxf(v, 0.f);
            Y[idx] = v;
        }
    }
}

__global__ void __launch_bounds__(256) conv_img_kernel(
    const float* __restrict__ X, const float* __restrict__ W,
    const float* __restrict__ bias,
    float* __restrict__ out_img, float* __restrict__ out_raw)
{
    const int b = blockIdx.y, y0 = blockIdx.x * 4, tid = threadIdx.x;
    const int r = tid >> 6, x = tid & 63;
    __shared__ float sW[3 * 1152];
    __shared__ float sIn[6][66];
    for (int i = tid; i < 3 * 1152; i += 256) sW[i] = W[i];
    float acc[3] = {0.f, 0.f, 0.f};
    const float* Xb = X + (size_t)b * NF * NPIX;
    for (int ci = 0; ci < NF; ci++) {
        __syncthreads();
        for (int i = tid; i < 6 * 66; i += 256) {
            int ry = i / 66, cx = i - ry * 66;
            int gy = y0 - 1 + ry, gx = cx - 1;
            float v = 0.f;
            if ((unsigned)gy < 64u && (unsigned)gx < 64u)
                v = Xb[(size_t)ci * NPIX + gy * 64 + gx];
            sIn[ry][cx] = v;
        }
        __syncthreads();
        float in[9];
#pragma unroll
        for (int dy = 0; dy < 3; dy++)
#pragma unroll
            for (int dx = 0; dx < 3; dx++) in[dy * 3 + dx] = sIn[r + dy][x + dx];
#pragma unroll
        for (int o = 0; o < 3; o++)
#pragma unroll
            for (int j = 0; j < 9; j++)
                acc[o] = fmaf(in[j], sW[o * 1152 + ci * 9 + j], acc[o]);
    }
#pragma unroll
    for (int o = 0; o < 3; o++) {
        float v = acc[o] + bias[o];
        size_t idx = ((size_t)b * 3 + o) * NPIX + (size_t)(y0 + r) * 64 + x;
        out_raw[idx] = v;
        out_img[idx] = fminf(fmaxf(v, -1.f), 1.f);
    }
}

// ======================================================================
extern "C" void kernel_launch(void* const* d_in, const int* in_sizes, int n_in,
                              void* d_out, int out_size)
{
    const float* lat  = (const float*)d_in[0];
    const float* ca   = (const float*)d_in[1];
    const float* leak = (const float*)d_in[2];
    const float* hw   = (const float*)d_in[3];
    const float* hb   = (const float*)d_in[4];
    const float* rw1  = (const float*)d_in[5];
    const float* rb1  = (const float*)d_in[6];
    const float* rw2  = (const float*)d_in[7];
    const float* rb2  = (const float*)d_in[8];
    const float* iw   = (const float*)d_in[9];
    const float* ib   = (const float*)d_in[10];

    float* out = (float*)d_out;
    float* out_img = out;
    float* embs    = out + 98304;
    float* out_raw = out + 98304 + (size_t)17 * 4194304;

    float *kall, *c1, *c2;
    __nv_bfloat16 *ph, *pl, *h1h, *h1l, *h2h, *h2l;
    __nv_bfloat16 *w1h, *w1l, *w2h, *w2l, *w3h, *w3l;
    cudaGetSymbolAddress((void**)&kall, g_kall);
    cudaGetSymbolAddress((void**)&ph,  g_ph);  cudaGetSymbolAddress((void**)&pl,  g_pl);
    cudaGetSymbolAddress((void**)&h1h, g_h1h); cudaGetSymbolAddress((void**)&h1l, g_h1l);
    cudaGetSymbolAddress((void**)&h2h, g_h2h); cudaGetSymbolAddress((void**)&h2l, g_h2l);
    cudaGetSymbolAddress((void**)&w1h, g_w1h); cudaGetSymbolAddress((void**)&w1l, g_w1l);
    cudaGetSymbolAddress((void**)&w2h, g_w2h); cudaGetSymbolAddress((void**)&w2l, g_w2l);
    cudaGetSymbolAddress((void**)&w3h, g_w3h); cudaGetSymbolAddress((void**)&w3l, g_w3l);
    cudaGetSymbolAddress((void**)&c1, g_c1);
    cudaGetSymbolAddress((void**)&c2, g_c2);

    // smem: MBLKS=1 staging 2*(2*128*40 + 2*32*136)*2B = 75776; epi 67584
    // smem: MBLKS=2 staging 2*(2*256*40 + 2*32*72)*2B = 100352; epi 69632
    const int SM1 = 75776;
    const int SM2 = 100352;
    cudaFuncSetAttribute(gemm_wmma<1>, cudaFuncAttributeMaxDynamicSharedMemorySize, SM1);
    cudaFuncSetAttribute(gemm_wmma<2>, cudaFuncAttributeMaxDynamicSharedMemorySize, SM2);

    hyper_kernel<<<KT / 256, 256>>>(lat, hw, hb, kall);
    pack_w_kernel<<<dim3(768, NB), 256>>>(kall);
    cudaMemcpyAsync(embs, ca, (size_t)4194304 * sizeof(float), cudaMemcpyDeviceToDevice);

    for (int t = 0; t < NCALLS; t++) {
        float* x  = embs + (size_t)t * 4194304;
        float* xn = x + 4194304;

        build_p_kernel<<<dim3(NF, NB), 256>>>(x, ph, pl);
        // h1 = relu(W_in @ p + b_in)
        gemm_wmma<1><<<dim3(32, NB), 256, SM1>>>(
            w1h, w1l, 384, ph, pl, 384, nullptr, nullptr,
            kall, OFF_BIN, 0, nullptr, h1h, h1l, nullptr, nullptr);
        // h2 = relu(W_mid @ h1 + b_mid)
        gemm_wmma<1><<<dim3(32, NB), 256, SM1>>>(
            w2h, w2l, 128, h1h, h1l, 128, nullptr, nullptr,
            kall, OFF_BMID, 0, nullptr, h2h, h2l, nullptr, nullptr);
        // dn = W_out@h2 + W_sh@p (+biases); xn = x + leak*val*sigmoid(gate)
        gemm_wmma<2><<<dim3(64, NB), 256, SM2>>>(
            w3h, w3l, 512, h2h, h2l, 128, ph, pl,
            kall, OFF_BOUT, OFF_BSH, xn, nullptr, nullptr, x, leak);
    }

    float* xf = embs + (size_t)NCALLS * 4194304;
    conv3x3_kernel<<<dim3(16, 4, NB), 256>>>(xf, rw1, rb1, nullptr, c1, 1);
    conv3x3_kernel<<<dim3(16, 4, NB), 256>>>(c1, rw2, rb2, xf, c2, 0);
    conv_img_kernel<<<dim3(16, NB), 256>>>(c2, iw, ib, out_img, out_raw);
}